// round 9
// baseline (speedup 1.0000x reference)
#include <cuda_runtime.h>

// GCN_18760417149681 — fully linear GraphSAGE collapse, v9: one persistent kernel
// with a contention-free flag-array grid barrier (R8's single-counter barrier
// serialized 888 atomics on one L2 address ≈ 15us/barrier — replaced).
// out[m] = inv[m]*(SB[m] + SG[m]) + xs[m] + (deg[m]>0)*CB + C2
//   ACC[m] = (SA, deg, SG, xs);  scatter1: ACC[dst] += (xp[src], 1, xg[src], 0)
//   scatter2: SB[dst] += SA[src]/max(deg[src],1)

#define NMAX  100000
#define EMAX  1600000
#define NFEAT 64
#define NHID  128
#define TPB   256
#define NBLK  888     // 6 * 148 — fully resident at <=42 regs/thread

__device__ __align__(16) float g_P[NFEAT];
__device__ __align__(16) float g_G[NFEAT];
__device__ __align__(16) float g_S[NFEAT];
__device__ float g_C[2];
__device__ int   g_ready = 0;    // prep-done flag (rewrites are value-identical)

__device__ __align__(16) float4 g_ACC[NMAX];   // (SA, deg, SG, xs)
__device__ __align__(8)  float2 g_XPG[NMAX];   // (xp, xg)
__device__ float g_SB[NMAX];
__device__ __align__(16) int2  g_EDGE[EMAX];   // packed (src, dst)

// ---- flag-array grid barrier (monotone phases; replay-safe via g_epoch) ----
__device__ unsigned g_epoch = 0;                 // bumped once per kernel call
__device__ volatile unsigned g_gen = 0;
__device__ volatile unsigned g_flags[NBLK];      // zero-init; monotone forever

__device__ __forceinline__ void grid_barrier(unsigned phase)
{
    __syncthreads();
    if (blockIdx.x == 0) {
        // 256 threads poll ~4 flags each — no shared hot address
        for (int i = threadIdx.x; i < NBLK; i += TPB) {
            if (i != 0) {
                while (g_flags[i] < phase) { __nanosleep(32); }
            }
        }
        __syncthreads();
        if (threadIdx.x == 0) {
            __threadfence();        // acquire others' work / release block0's
            g_gen = phase;
        }
    } else {
        if (threadIdx.x == 0) {
            __threadfence();        // release this block's phase work
            g_flags[blockIdx.x] = phase;
            while (g_gen < phase) { __nanosleep(32); }
            __threadfence();        // acquire
        }
    }
    __syncthreads();
}

// ---- dtype sniff: int64 LE small indices => odd 32-bit words all zero ----
__device__ __forceinline__ int sniff_is64(const int* __restrict__ ei32, int E)
{
    int odd_nonzero = 0;
    #pragma unroll 1
    for (int k = 0; k < 32; k++) {
        long long pos = (1 + (long long)k * ((2LL * E - 2) / 32)) | 1;
        if (ei32[pos] != 0) odd_nonzero++;
    }
    return (odd_nonzero == 0) ? 1 : 0;
}

__global__ void __launch_bounds__(TPB, 6) k_all(
    const float* __restrict__ x, const int* __restrict__ ei32,
    const float* __restrict__ Wl1, const float* __restrict__ Wr1,
    const float* __restrict__ b1,
    const float* __restrict__ Wl2, const float* __restrict__ Wr2,
    const float* __restrict__ b2,
    const float* __restrict__ Wfc1, const float* __restrict__ bfc1,
    const float* __restrict__ Wfc2, const float* __restrict__ bfc2,
    float* __restrict__ out, int N, int E)
{
    const int b = blockIdx.x;
    const int t = threadIdx.x;
    const unsigned tid = b * TPB + t;
    const unsigned T   = NBLK * TPB;

    // epoch gives this call's monotone phase base (prev call's bump is visible
    // at launch boundary; all blocks read the same value)
    const unsigned pbase = *(volatile unsigned*)&g_epoch * 4u;

    // ============ phase 0a: prep (block 0) | edge decode (blocks 1..) ============
    if (b == 0) {
        __shared__ float sw[NHID], su[NHID], sv[NHID];
        if (t < NHID) {
            float acc = 0.f;
            #pragma unroll
            for (int c = 0; c < 32; c++) acc += Wfc1[t * 32 + c] * Wfc2[c];
            sw[t] = acc;
        }
        __syncthreads();
        if (t < NHID) {
            float au = 0.f, av = 0.f;
            #pragma unroll 4
            for (int j = 0; j < NHID; j++) {
                float wv = sw[j];
                au += Wl2[t * NHID + j] * wv;
                av += Wr2[t * NHID + j] * wv;
            }
            su[t] = au; sv[t] = av;
        }
        __syncthreads();
        if (t < NFEAT) {
            float p = 0.f, g = 0.f, s = 0.f;
            #pragma unroll 4
            for (int j = 0; j < NHID; j++) {
                float wl = Wl1[t * NHID + j];
                float wr = Wr1[t * NHID + j];
                float uj = su[j], vj = sv[j];
                p += wl * uj;
                g += wr * uj + wl * vj;
                s += wr * vj;
            }
            g_P[t] = p; g_G[t] = g; g_S[t] = s;
        }
        if (t == 0) {
            float cb = 0.f, c2 = 0.f;
            for (int j = 0; j < NHID; j++) {
                cb += b1[j] * su[j];
                c2 += b1[j] * sv[j] + b2[j] * sw[j];
            }
            for (int c = 0; c < 32; c++) c2 += bfc1[c] * Wfc2[c];
            c2 += bfc2[0];
            g_C[0] = cb; g_C[1] = c2;
        }
        __syncthreads();
        if (t == 0) {
            __threadfence();
            atomicExch(&g_ready, 1);
        }
    } else {
        __shared__ int s_is64;
        if (t == 0) s_is64 = sniff_is64(ei32, E);
        __syncthreads();
        int is64 = s_is64;
        const long long stride = (long long)(NBLK - 1) * TPB * 4;
        for (long long base = ((long long)(b - 1) * TPB + t) * 4; base < E;
             base += stride) {
            if (base + 3 < E) {
                int s[4], d[4];
                if (is64) {
                    const long long* p = (const long long*)ei32;
                    longlong2 a0 = __ldg((const longlong2*)(p + base));
                    longlong2 a1 = __ldg((const longlong2*)(p + base + 2));
                    longlong2 c0 = __ldg((const longlong2*)(p + E + base));
                    longlong2 c1 = __ldg((const longlong2*)(p + E + base + 2));
                    s[0] = (int)a0.x; s[1] = (int)a0.y; s[2] = (int)a1.x; s[3] = (int)a1.y;
                    d[0] = (int)c0.x; d[1] = (int)c0.y; d[2] = (int)c1.x; d[3] = (int)c1.y;
                } else {
                    int4 a = __ldg((const int4*)(ei32 + base));
                    int4 c = __ldg((const int4*)(ei32 + E + base));
                    s[0] = a.x; s[1] = a.y; s[2] = a.z; s[3] = a.w;
                    d[0] = c.x; d[1] = c.y; d[2] = c.z; d[3] = c.w;
                }
                #pragma unroll
                for (int k = 0; k < 4; k++) {
                    s[k] = min(max(s[k], 0), N - 1);
                    d[k] = min(max(d[k], 0), N - 1);
                }
                ((int4*)g_EDGE)[(base >> 1)]     = make_int4(s[0], d[0], s[1], d[1]);
                ((int4*)g_EDGE)[(base >> 1) + 1] = make_int4(s[2], d[2], s[3], d[3]);
            } else {
                for (long long e = base; e < E; e++) {
                    int src, dst;
                    if (is64) {
                        src = (int)((const long long*)ei32)[e];
                        dst = (int)((const long long*)ei32)[E + e];
                    } else {
                        src = ei32[e]; dst = ei32[E + e];
                    }
                    g_EDGE[e] = make_int2(min(max(src, 0), N - 1),
                                          min(max(dst, 0), N - 1));
                }
            }
        }
    }

    // ============ phase 0b: passA (all blocks; wait for prep) ============
    if (t == 0) {
        while (*(volatile int*)&g_ready == 0) { __nanosleep(64); }
        __threadfence();
    }
    __syncthreads();
    {
        unsigned hw = tid >> 4, lane = t & 15, nhw = T >> 4;
        float4 pv = ((const float4*)g_P)[lane];
        float4 gv = ((const float4*)g_G)[lane];
        float4 sv = ((const float4*)g_S)[lane];
        for (unsigned node = hw; node < (unsigned)N; node += nhw) {
            float4 xv = __ldg(((const float4*)x) + (size_t)node * 16 + lane);
            float xp = xv.x * pv.x + xv.y * pv.y + xv.z * pv.z + xv.w * pv.w;
            float xg = xv.x * gv.x + xv.y * gv.y + xv.z * gv.z + xv.w * gv.w;
            float xs = xv.x * sv.x + xv.y * sv.y + xv.z * sv.z + xv.w * sv.w;
            #pragma unroll
            for (int off = 8; off; off >>= 1) {
                xp += __shfl_xor_sync(0xffffffffu, xp, off);
                xg += __shfl_xor_sync(0xffffffffu, xg, off);
                xs += __shfl_xor_sync(0xffffffffu, xs, off);
            }
            if (lane == 0) {
                g_XPG[node] = make_float2(xp, xg);
                g_ACC[node] = make_float4(0.f, 0.f, 0.f, xs);
                g_SB[node]  = 0.f;
            }
        }
    }
    grid_barrier(pbase + 1);

    // ============ phase 1: scatter1 — ACC[dst] += (xp, 1, xg, 0) ============
    {
        const long long stride = (long long)T * 4;
        for (long long base = (long long)tid * 4; base < E; base += stride) {
            if (base + 3 < E) {
                int4 q0 = ((const int4*)g_EDGE)[base >> 1];
                int4 q1 = ((const int4*)g_EDGE)[(base >> 1) + 1];
                float2 v0 = __ldg(&g_XPG[q0.x]);
                float2 v1 = __ldg(&g_XPG[q0.z]);
                float2 v2 = __ldg(&g_XPG[q1.x]);
                float2 v3 = __ldg(&g_XPG[q1.z]);
                atomicAdd(&g_ACC[q0.y], make_float4(v0.x, 1.f, v0.y, 0.f));
                atomicAdd(&g_ACC[q0.w], make_float4(v1.x, 1.f, v1.y, 0.f));
                atomicAdd(&g_ACC[q1.y], make_float4(v2.x, 1.f, v2.y, 0.f));
                atomicAdd(&g_ACC[q1.w], make_float4(v3.x, 1.f, v3.y, 0.f));
            } else {
                for (long long e = base; e < E; e++) {
                    int2 ed = g_EDGE[e];
                    float2 v = __ldg(&g_XPG[ed.x]);
                    atomicAdd(&g_ACC[ed.y], make_float4(v.x, 1.f, v.y, 0.f));
                }
            }
        }
    }
    grid_barrier(pbase + 2);

    // ============ phase 2: scatter2 — SB[dst] += SA[src]/max(deg,1) ============
    {
        const long long stride = (long long)T * 4;
        for (long long base = (long long)tid * 4; base < E; base += stride) {
            if (base + 3 < E) {
                int4 q0 = ((const int4*)g_EDGE)[base >> 1];
                int4 q1 = ((const int4*)g_EDGE)[(base >> 1) + 1];
                float2 a0 = __ldg((const float2*)&g_ACC[q0.x]);
                float2 a1 = __ldg((const float2*)&g_ACC[q0.z]);
                float2 a2 = __ldg((const float2*)&g_ACC[q1.x]);
                float2 a3 = __ldg((const float2*)&g_ACC[q1.z]);
                atomicAdd(&g_SB[q0.y], a0.x * __frcp_rn(fmaxf(a0.y, 1.f)));
                atomicAdd(&g_SB[q0.w], a1.x * __frcp_rn(fmaxf(a1.y, 1.f)));
                atomicAdd(&g_SB[q1.y], a2.x * __frcp_rn(fmaxf(a2.y, 1.f)));
                atomicAdd(&g_SB[q1.w], a3.x * __frcp_rn(fmaxf(a3.y, 1.f)));
            } else {
                for (long long e = base; e < E; e++) {
                    int2 ed = g_EDGE[e];
                    float2 a = __ldg((const float2*)&g_ACC[ed.x]);
                    atomicAdd(&g_SB[ed.y], a.x * __frcp_rn(fmaxf(a.y, 1.f)));
                }
            }
        }
    }
    grid_barrier(pbase + 3);

    // ============ phase 3: final ============
    {
        float cb = g_C[0], c2 = g_C[1];
        for (unsigned i = tid; i < (unsigned)N; i += T) {
            float4 a = g_ACC[i];                 // (SA, deg, SG, xs)
            float inv = __frcp_rn(fmaxf(a.y, 1.f));
            float res = inv * (g_SB[i] + a.z) + a.w + c2;
            if (a.y > 0.f) res += cb;
            out[i] = res;
        }
    }

    // bump epoch for next call (visible at next launch boundary)
    if (b == 0 && t == 0) {
        __threadfence();
        g_epoch = (pbase / 4u) + 1u;
    }
}

// ===================== launch =====================
extern "C" void kernel_launch(void* const* d_in, const int* in_sizes, int n_in,
                              void* d_out, int out_size)
{
    const float* x    = (const float*)d_in[0];
    const int*   ei32 = (const int*)d_in[1];
    // d_in[2] = edge_weight (unused by the reference)
    const float* Wl1  = (const float*)d_in[3];
    const float* Wr1  = (const float*)d_in[4];
    const float* b1   = (const float*)d_in[5];
    const float* Wl2  = (const float*)d_in[6];
    const float* Wr2  = (const float*)d_in[7];
    const float* b2   = (const float*)d_in[8];
    const float* Wfc1 = (const float*)d_in[9];
    const float* bfc1 = (const float*)d_in[10];
    const float* Wfc2 = (const float*)d_in[11];
    const float* bfc2 = (const float*)d_in[12];
    float* out = (float*)d_out;

    int N = in_sizes[0] / NFEAT;   // 100000
    int E = in_sizes[2];           // 1600000

    k_all<<<NBLK, TPB>>>(x, ei32, Wl1, Wr1, b1, Wl2, Wr2, b2,
                         Wfc1, bfc1, Wfc2, bfc2, out, N, E);
}

// round 10
// speedup vs baseline: 1.0545x; 1.0545x over previous
#include <cuda_runtime.h>

// GCN_18760417149681 — fully linear GraphSAGE collapse, v10 (4 launches).
// out[m] = inv[m]*(SB[m] + SG[m]) + xs[m] + (deg[m]>0)*CB + C2
//   ACC[m] = (SA, deg, SG, xs);  scatter1: ACC[dst] += (xp[src], 1, xg[src], 0)
//   scatter2: SB[dst] += SA[src]/max(deg[src],1)
// v10: decode pass folded into scatter1 (reads raw idx, streams packed EDGE
// for scatter2); k_init is just weight-collapse + passA.

#define NMAX  100000
#define EMAX  1600000
#define NFEAT 64
#define NHID  128

__device__ __align__(16) float g_P[NFEAT];
__device__ __align__(16) float g_G[NFEAT];
__device__ __align__(16) float g_S[NFEAT];
__device__ float g_C[2];        // [0]=cb (gated by deg>0), [1]=c2
__device__ int   g_ready = 0;   // prep-done flag (rewrites value-identical)

__device__ __align__(16) float4 g_ACC[NMAX];   // (SA, deg, SG, xs)
__device__ __align__(8)  float2 g_XPG[NMAX];   // (xp, xg)
__device__ float g_SB[NMAX];
__device__ __align__(16) int2  g_EDGE[EMAX];   // packed (src, dst), written by scatter1

// ---- dtype sniff: int64 LE small indices => odd 32-bit words all zero ----
__device__ __forceinline__ int sniff_is64(const int* __restrict__ ei32, int E)
{
    int odd_nonzero = 0;
    #pragma unroll 1
    for (int k = 0; k < 32; k++) {
        long long pos = (1 + (long long)k * ((2LL * E - 2) / 32)) | 1;
        if (ei32[pos] != 0) odd_nonzero++;
    }
    return (odd_nonzero == 0) ? 1 : 0;
}

// ===================== launch 1: prep (block 0) + passA =====================
__global__ void __launch_bounds__(256) k_init(
    const float* __restrict__ x,
    const float* __restrict__ Wl1, const float* __restrict__ Wr1,
    const float* __restrict__ b1,
    const float* __restrict__ Wl2, const float* __restrict__ Wr2,
    const float* __restrict__ b2,
    const float* __restrict__ Wfc1, const float* __restrict__ bfc1,
    const float* __restrict__ Wfc2, const float* __restrict__ bfc2,
    int N)
{
    int b = blockIdx.x;
    int t = threadIdx.x;

    if (b == 0) {
        __shared__ float sw[NHID], su[NHID], sv[NHID];
        if (t < NHID) {
            float acc = 0.f;
            #pragma unroll
            for (int c = 0; c < 32; c++) acc += Wfc1[t * 32 + c] * Wfc2[c];
            sw[t] = acc;
        }
        __syncthreads();
        if (t < NHID) {
            float au = 0.f, av = 0.f;
            #pragma unroll 4
            for (int j = 0; j < NHID; j++) {
                float wv = sw[j];
                au += Wl2[t * NHID + j] * wv;
                av += Wr2[t * NHID + j] * wv;
            }
            su[t] = au; sv[t] = av;
        }
        __syncthreads();
        if (t < NFEAT) {
            float p = 0.f, g = 0.f, s = 0.f;
            #pragma unroll 4
            for (int j = 0; j < NHID; j++) {
                float wl = Wl1[t * NHID + j];
                float wr = Wr1[t * NHID + j];
                float uj = su[j], vj = sv[j];
                p += wl * uj;
                g += wr * uj + wl * vj;
                s += wr * vj;
            }
            g_P[t] = p; g_G[t] = g; g_S[t] = s;
        }
        if (t == 0) {
            float cb = 0.f, c2 = 0.f;
            for (int j = 0; j < NHID; j++) {
                cb += b1[j] * su[j];
                c2 += b1[j] * sv[j] + b2[j] * sw[j];
            }
            for (int c = 0; c < 32; c++) c2 += bfc1[c] * Wfc2[c];
            c2 += bfc2[0];
            g_C[0] = cb; g_C[1] = c2;
        }
        __syncthreads();
        if (t == 0) {
            __threadfence();
            atomicExch(&g_ready, 1);
        }
        return;
    }

    // passA blocks: wait until prep published p/g/s
    if (t == 0) {
        while (*(volatile int*)&g_ready == 0) { __nanosleep(64); }
        __threadfence();
    }
    __syncthreads();

    int node = (b - 1) * 16 + (t >> 4);      // half-warp per node
    int lane = t & 15;
    if (node >= N) return;

    float4 xv = __ldg(((const float4*)x) + (long long)node * 16 + lane);
    float4 pv = ((const float4*)g_P)[lane];
    float4 gv = ((const float4*)g_G)[lane];
    float4 sv = ((const float4*)g_S)[lane];

    float xp = xv.x * pv.x + xv.y * pv.y + xv.z * pv.z + xv.w * pv.w;
    float xg = xv.x * gv.x + xv.y * gv.y + xv.z * gv.z + xv.w * gv.w;
    float xs = xv.x * sv.x + xv.y * sv.y + xv.z * sv.z + xv.w * sv.w;

    #pragma unroll
    for (int off = 8; off; off >>= 1) {
        xp += __shfl_xor_sync(0xffffffffu, xp, off);
        xg += __shfl_xor_sync(0xffffffffu, xg, off);
        xs += __shfl_xor_sync(0xffffffffu, xs, off);
    }
    if (lane == 0) {
        g_XPG[node] = make_float2(xp, xg);
        g_ACC[node] = make_float4(0.f, 0.f, 0.f, xs);
        g_SB[node]  = 0.f;
    }
}

// ===================== scatter 1: raw idx -> RED.128 + packed EDGE out ===========
__global__ void __launch_bounds__(256) k_scatter1(const int* __restrict__ ei32,
                                                  int N, int E)
{
    __shared__ int s_is64;
    if (threadIdx.x == 0) s_is64 = sniff_is64(ei32, E);
    __syncthreads();
    int is64 = s_is64;

    long long base = (long long)(blockIdx.x * 256 + threadIdx.x) * 4;
    if (base >= E) return;

    if (base + 3 < E) {
        int s[4], d[4];
        if (is64) {
            const long long* p = (const long long*)ei32;
            longlong2 a0 = __ldg((const longlong2*)(p + base));
            longlong2 a1 = __ldg((const longlong2*)(p + base + 2));
            longlong2 c0 = __ldg((const longlong2*)(p + E + base));
            longlong2 c1 = __ldg((const longlong2*)(p + E + base + 2));
            s[0] = (int)a0.x; s[1] = (int)a0.y; s[2] = (int)a1.x; s[3] = (int)a1.y;
            d[0] = (int)c0.x; d[1] = (int)c0.y; d[2] = (int)c1.x; d[3] = (int)c1.y;
        } else {
            int4 a = __ldg((const int4*)(ei32 + base));
            int4 c = __ldg((const int4*)(ei32 + E + base));
            s[0] = a.x; s[1] = a.y; s[2] = a.z; s[3] = a.w;
            d[0] = c.x; d[1] = c.y; d[2] = c.z; d[3] = c.w;
        }
        #pragma unroll
        for (int k = 0; k < 4; k++) {
            s[k] = min(max(s[k], 0), N - 1);
            d[k] = min(max(d[k], 0), N - 1);
        }
        // stream packed edges for scatter2 (coalesced, 8B/edge)
        ((int4*)g_EDGE)[(base >> 1)]     = make_int4(s[0], d[0], s[1], d[1]);
        ((int4*)g_EDGE)[(base >> 1) + 1] = make_int4(s[2], d[2], s[3], d[3]);

        float2 v0 = __ldg(&g_XPG[s[0]]);
        float2 v1 = __ldg(&g_XPG[s[1]]);
        float2 v2 = __ldg(&g_XPG[s[2]]);
        float2 v3 = __ldg(&g_XPG[s[3]]);
        atomicAdd(&g_ACC[d[0]], make_float4(v0.x, 1.f, v0.y, 0.f));
        atomicAdd(&g_ACC[d[1]], make_float4(v1.x, 1.f, v1.y, 0.f));
        atomicAdd(&g_ACC[d[2]], make_float4(v2.x, 1.f, v2.y, 0.f));
        atomicAdd(&g_ACC[d[3]], make_float4(v3.x, 1.f, v3.y, 0.f));
    } else {
        for (long long e = base; e < E; e++) {
            int src, dst;
            if (is64) {
                src = (int)((const long long*)ei32)[e];
                dst = (int)((const long long*)ei32)[E + e];
            } else {
                src = ei32[e]; dst = ei32[E + e];
            }
            src = min(max(src, 0), N - 1);
            dst = min(max(dst, 0), N - 1);
            g_EDGE[e] = make_int2(src, dst);
            float2 v = __ldg(&g_XPG[src]);
            atomicAdd(&g_ACC[dst], make_float4(v.x, 1.f, v.y, 0.f));
        }
    }
}

// ===================== scatter 2: SB[dst] += SA[src]/max(deg,1) ==============
__global__ void __launch_bounds__(256) k_scatter2(int E)
{
    long long base = (long long)(blockIdx.x * 256 + threadIdx.x) * 4;
    if (base >= E) return;

    if (base + 3 < E) {
        int4 q0 = ((const int4*)g_EDGE)[base >> 1];        // (s0,d0,s1,d1)
        int4 q1 = ((const int4*)g_EDGE)[(base >> 1) + 1];  // (s2,d2,s3,d3)
        float2 a0 = __ldg((const float2*)&g_ACC[q0.x]);    // (SA, deg)
        float2 a1 = __ldg((const float2*)&g_ACC[q0.z]);
        float2 a2 = __ldg((const float2*)&g_ACC[q1.x]);
        float2 a3 = __ldg((const float2*)&g_ACC[q1.z]);
        atomicAdd(&g_SB[q0.y], a0.x * __frcp_rn(fmaxf(a0.y, 1.f)));
        atomicAdd(&g_SB[q0.w], a1.x * __frcp_rn(fmaxf(a1.y, 1.f)));
        atomicAdd(&g_SB[q1.y], a2.x * __frcp_rn(fmaxf(a2.y, 1.f)));
        atomicAdd(&g_SB[q1.w], a3.x * __frcp_rn(fmaxf(a3.y, 1.f)));
    } else {
        for (long long e = base; e < E; e++) {
            int2 ed = g_EDGE[e];
            float2 a = __ldg((const float2*)&g_ACC[ed.x]);
            atomicAdd(&g_SB[ed.y], a.x * __frcp_rn(fmaxf(a.y, 1.f)));
        }
    }
}

// ===================== final =====================
__global__ void __launch_bounds__(256) k_final(float* __restrict__ out, int n)
{
    int i = blockIdx.x * blockDim.x + threadIdx.x;
    if (i < n) {
        float cb = g_C[0], c2 = g_C[1];
        float4 a = g_ACC[i];                 // (SA, deg, SG, xs)
        float inv = __frcp_rn(fmaxf(a.y, 1.f));
        float res = inv * (g_SB[i] + a.z) + a.w + c2;
        if (a.y > 0.f) res += cb;
        out[i] = res;
    }
}

// ===================== launch =====================
extern "C" void kernel_launch(void* const* d_in, const int* in_sizes, int n_in,
                              void* d_out, int out_size)
{
    const float* x    = (const float*)d_in[0];
    const int*   ei32 = (const int*)d_in[1];
    // d_in[2] = edge_weight (unused by the reference)
    const float* Wl1  = (const float*)d_in[3];
    const float* Wr1  = (const float*)d_in[4];
    const float* b1   = (const float*)d_in[5];
    const float* Wl2  = (const float*)d_in[6];
    const float* Wr2  = (const float*)d_in[7];
    const float* b2   = (const float*)d_in[8];
    const float* Wfc1 = (const float*)d_in[9];
    const float* bfc1 = (const float*)d_in[10];
    const float* Wfc2 = (const float*)d_in[11];
    const float* bfc2 = (const float*)d_in[12];
    float* out = (float*)d_out;

    int N = in_sizes[0] / NFEAT;   // 100000
    int E = in_sizes[2];           // 1600000

    int aB = (N + 15) / 16;                // passA blocks (16 nodes/block)
    int eB = (E + 1023) / 1024;            // scatter blocks (4 edges/thread)

    k_init<<<1 + aB, 256>>>(x, Wl1, Wr1, b1, Wl2, Wr2, b2,
                            Wfc1, bfc1, Wfc2, bfc2, N);
    k_scatter1<<<eB, 256>>>(ei32, N, E);
    k_scatter2<<<eB, 256>>>(E);
    k_final<<<(N + 255) / 256, 256>>>(out, N);
}

// round 11
// speedup vs baseline: 1.2842x; 1.2178x over previous
#include <cuda_runtime.h>

// GCN_18760417149681 — fully linear GraphSAGE collapse, v11 = R7 + PDL.
// out[m] = inv[m]*(SB[m] + SG[m]) + xs[m] + (deg[m]>0)*CB + C2
//   ACC[m] = (SA, deg, SG, xs);  scatter1: ACC[dst] += (xp[src], 1, xg[src], 0)
//   scatter2: SB[dst] += SA[src]/max(deg[src],1)
// Four kernels (standalone speeds) chained with programmatic dependent launch
// so successor prologues overlap predecessor drains.

#define NMAX  100000
#define EMAX  1600000
#define NFEAT 64
#define NHID  128

__device__ __align__(16) float g_P[NFEAT];
__device__ __align__(16) float g_G[NFEAT];
__device__ __align__(16) float g_S[NFEAT];
__device__ float g_C[2];        // [0]=cb (gated by deg>0), [1]=c2
__device__ int   g_ready = 0;   // prep-done flag (rewrites value-identical)

__device__ __align__(16) float4 g_ACC[NMAX];   // (SA, deg, SG, xs)
__device__ __align__(8)  float2 g_XPG[NMAX];   // (xp, xg)
__device__ float g_SB[NMAX];
__device__ __align__(16) int2  g_EDGE[EMAX];   // packed (src, dst)

// ---- dtype sniff: int64 LE small indices => odd 32-bit words all zero ----
__device__ __forceinline__ int sniff_is64(const int* __restrict__ ei32, int E)
{
    int odd_nonzero = 0;
    #pragma unroll 1
    for (int k = 0; k < 32; k++) {
        long long pos = (1 + (long long)k * ((2LL * E - 2) / 32)) | 1;
        if (ei32[pos] != 0) odd_nonzero++;
    }
    return (odd_nonzero == 0) ? 1 : 0;
}

// ===================== launch 1: prep + decode + passA =====================
__global__ void __launch_bounds__(256) k_init(
    const float* __restrict__ x, const int* __restrict__ ei32,
    const float* __restrict__ Wl1, const float* __restrict__ Wr1,
    const float* __restrict__ b1,
    const float* __restrict__ Wl2, const float* __restrict__ Wr2,
    const float* __restrict__ b2,
    const float* __restrict__ Wfc1, const float* __restrict__ bfc1,
    const float* __restrict__ Wfc2, const float* __restrict__ bfc2,
    int N, int E, int decBlocks)
{
    int b = blockIdx.x;

    // -------- block 0: weight collapse --------
    if (b == 0) {
        __shared__ float sw[NHID], su[NHID], sv[NHID];
        int t = threadIdx.x;
        if (t < NHID) {
            float acc = 0.f;
            #pragma unroll
            for (int c = 0; c < 32; c++) acc += Wfc1[t * 32 + c] * Wfc2[c];
            sw[t] = acc;
        }
        __syncthreads();
        if (t < NHID) {
            float au = 0.f, av = 0.f;
            #pragma unroll 4
            for (int j = 0; j < NHID; j++) {
                float wv = sw[j];
                au += Wl2[t * NHID + j] * wv;
                av += Wr2[t * NHID + j] * wv;
            }
            su[t] = au; sv[t] = av;
        }
        __syncthreads();
        if (t < NFEAT) {
            float p = 0.f, g = 0.f, s = 0.f;
            #pragma unroll 4
            for (int j = 0; j < NHID; j++) {
                float wl = Wl1[t * NHID + j];
                float wr = Wr1[t * NHID + j];
                float uj = su[j], vj = sv[j];
                p += wl * uj;
                g += wr * uj + wl * vj;
                s += wr * vj;
            }
            g_P[t] = p; g_G[t] = g; g_S[t] = s;
        }
        if (t == 0) {
            float cb = 0.f, c2 = 0.f;
            for (int j = 0; j < NHID; j++) {
                cb += b1[j] * su[j];
                c2 += b1[j] * sv[j] + b2[j] * sw[j];
            }
            for (int c = 0; c < 32; c++) c2 += bfc1[c] * Wfc2[c];
            c2 += bfc2[0];
            g_C[0] = cb; g_C[1] = c2;
        }
        __syncthreads();
        if (t == 0) {
            __threadfence();                 // release g_P/g_G/g_S/g_C
            atomicExch(&g_ready, 1);
        }
        cudaTriggerProgrammaticLaunchCompletion();
        return;
    }

    // -------- blocks [1, decBlocks]: edge decode to packed int2 --------
    if (b <= decBlocks) {
        __shared__ int s_is64;
        if (threadIdx.x == 0) s_is64 = sniff_is64(ei32, E);
        __syncthreads();
        int is64 = s_is64;

        long long base = ((long long)(b - 1) * 256 + threadIdx.x) * 4;
        if (base < E) {
            if (base + 3 < E) {
                int s[4], d[4];
                if (is64) {
                    const long long* p = (const long long*)ei32;
                    longlong2 a = __ldg((const longlong2*)(p + base));
                    longlong2 c = __ldg((const longlong2*)(p + base + 2));
                    longlong2 e = __ldg((const longlong2*)(p + E + base));
                    longlong2 f = __ldg((const longlong2*)(p + E + base + 2));
                    s[0] = (int)a.x; s[1] = (int)a.y; s[2] = (int)c.x; s[3] = (int)c.y;
                    d[0] = (int)e.x; d[1] = (int)e.y; d[2] = (int)f.x; d[3] = (int)f.y;
                } else {
                    int4 a = __ldg((const int4*)(ei32 + base));
                    int4 c = __ldg((const int4*)(ei32 + E + base));
                    s[0] = a.x; s[1] = a.y; s[2] = a.z; s[3] = a.w;
                    d[0] = c.x; d[1] = c.y; d[2] = c.z; d[3] = c.w;
                }
                #pragma unroll
                for (int k = 0; k < 4; k++) {
                    s[k] = min(max(s[k], 0), N - 1);
                    d[k] = min(max(d[k], 0), N - 1);
                }
                ((int4*)g_EDGE)[(base >> 1)]     = make_int4(s[0], d[0], s[1], d[1]);
                ((int4*)g_EDGE)[(base >> 1) + 1] = make_int4(s[2], d[2], s[3], d[3]);
            } else {
                for (long long e = base; e < E; e++) {
                    int src, dst;
                    if (is64) {
                        src = (int)((const long long*)ei32)[e];
                        dst = (int)((const long long*)ei32)[E + e];
                    } else {
                        src = ei32[e]; dst = ei32[E + e];
                    }
                    src = min(max(src, 0), N - 1);
                    dst = min(max(dst, 0), N - 1);
                    g_EDGE[e] = make_int2(src, dst);
                }
            }
        }
        cudaTriggerProgrammaticLaunchCompletion();
        return;
    }

    // -------- remaining blocks: passA (half-warp per node) --------
    if (threadIdx.x == 0) {
        while (*(volatile int*)&g_ready == 0) { __nanosleep(64); }
        __threadfence();                     // acquire
    }
    __syncthreads();

    int ab   = b - 1 - decBlocks;
    int node = ab * 16 + (threadIdx.x >> 4);
    int lane = threadIdx.x & 15;
    if (node < N) {
        float4 xv = __ldg(((const float4*)x) + (long long)node * 16 + lane);
        float4 pv = ((const float4*)g_P)[lane];
        float4 gv = ((const float4*)g_G)[lane];
        float4 sv = ((const float4*)g_S)[lane];

        float xp = xv.x * pv.x + xv.y * pv.y + xv.z * pv.z + xv.w * pv.w;
        float xg = xv.x * gv.x + xv.y * gv.y + xv.z * gv.z + xv.w * gv.w;
        float xs = xv.x * sv.x + xv.y * sv.y + xv.z * sv.z + xv.w * sv.w;

        #pragma unroll
        for (int off = 8; off; off >>= 1) {
            xp += __shfl_xor_sync(0xffffffffu, xp, off);
            xg += __shfl_xor_sync(0xffffffffu, xg, off);
            xs += __shfl_xor_sync(0xffffffffu, xs, off);
        }
        if (lane == 0) {
            g_XPG[node] = make_float2(xp, xg);
            g_ACC[node] = make_float4(0.f, 0.f, 0.f, xs);
            g_SB[node]  = 0.f;
        }
    }
    cudaTriggerProgrammaticLaunchCompletion();
}

// ===================== scatter 1: ACC[dst] += (xp, 1, xg, 0) =====================
__global__ void __launch_bounds__(256) k_scatter1(int E)
{
    cudaGridDependencySynchronize();

    long long base = (long long)(blockIdx.x * 256 + threadIdx.x) * 4;
    if (base < E) {
        if (base + 3 < E) {
            int4 q0 = ((const int4*)g_EDGE)[base >> 1];        // (s0,d0,s1,d1)
            int4 q1 = ((const int4*)g_EDGE)[(base >> 1) + 1];  // (s2,d2,s3,d3)
            float2 v0 = __ldg(&g_XPG[q0.x]);
            float2 v1 = __ldg(&g_XPG[q0.z]);
            float2 v2 = __ldg(&g_XPG[q1.x]);
            float2 v3 = __ldg(&g_XPG[q1.z]);
            atomicAdd(&g_ACC[q0.y], make_float4(v0.x, 1.f, v0.y, 0.f));
            atomicAdd(&g_ACC[q0.w], make_float4(v1.x, 1.f, v1.y, 0.f));
            atomicAdd(&g_ACC[q1.y], make_float4(v2.x, 1.f, v2.y, 0.f));
            atomicAdd(&g_ACC[q1.w], make_float4(v3.x, 1.f, v3.y, 0.f));
        } else {
            for (long long e = base; e < E; e++) {
                int2 ed = g_EDGE[e];
                float2 v = __ldg(&g_XPG[ed.x]);
                atomicAdd(&g_ACC[ed.y], make_float4(v.x, 1.f, v.y, 0.f));
            }
        }
    }
    cudaTriggerProgrammaticLaunchCompletion();
}

// ===================== scatter 2: SB[dst] += SA[src]/max(deg,1) ==============
__global__ void __launch_bounds__(256) k_scatter2(int E)
{
    cudaGridDependencySynchronize();

    long long base = (long long)(blockIdx.x * 256 + threadIdx.x) * 4;
    if (base < E) {
        if (base + 3 < E) {
            int4 q0 = ((const int4*)g_EDGE)[base >> 1];
            int4 q1 = ((const int4*)g_EDGE)[(base >> 1) + 1];
            float2 a0 = __ldg((const float2*)&g_ACC[q0.x]);    // (SA, deg)
            float2 a1 = __ldg((const float2*)&g_ACC[q0.z]);
            float2 a2 = __ldg((const float2*)&g_ACC[q1.x]);
            float2 a3 = __ldg((const float2*)&g_ACC[q1.z]);
            atomicAdd(&g_SB[q0.y], a0.x * __frcp_rn(fmaxf(a0.y, 1.f)));
            atomicAdd(&g_SB[q0.w], a1.x * __frcp_rn(fmaxf(a1.y, 1.f)));
            atomicAdd(&g_SB[q1.y], a2.x * __frcp_rn(fmaxf(a2.y, 1.f)));
            atomicAdd(&g_SB[q1.w], a3.x * __frcp_rn(fmaxf(a3.y, 1.f)));
        } else {
            for (long long e = base; e < E; e++) {
                int2 ed = g_EDGE[e];
                float2 a = __ldg((const float2*)&g_ACC[ed.x]);
                atomicAdd(&g_SB[ed.y], a.x * __frcp_rn(fmaxf(a.y, 1.f)));
            }
        }
    }
    cudaTriggerProgrammaticLaunchCompletion();
}

// ===================== final =====================
__global__ void __launch_bounds__(256) k_final(float* __restrict__ out, int n)
{
    cudaGridDependencySynchronize();

    int i = blockIdx.x * blockDim.x + threadIdx.x;
    if (i < n) {
        float cb = g_C[0], c2 = g_C[1];
        float4 a = g_ACC[i];                 // (SA, deg, SG, xs)
        float inv = __frcp_rn(fmaxf(a.y, 1.f));
        float res = inv * (g_SB[i] + a.z) + a.w + c2;
        if (a.y > 0.f) res += cb;
        out[i] = res;
    }
}

// ===================== launch =====================
extern "C" void kernel_launch(void* const* d_in, const int* in_sizes, int n_in,
                              void* d_out, int out_size)
{
    const float* x    = (const float*)d_in[0];
    const int*   ei32 = (const int*)d_in[1];
    // d_in[2] = edge_weight (unused by the reference)
    const float* Wl1  = (const float*)d_in[3];
    const float* Wr1  = (const float*)d_in[4];
    const float* b1   = (const float*)d_in[5];
    const float* Wl2  = (const float*)d_in[6];
    const float* Wr2  = (const float*)d_in[7];
    const float* b2   = (const float*)d_in[8];
    const float* Wfc1 = (const float*)d_in[9];
    const float* bfc1 = (const float*)d_in[10];
    const float* Wfc2 = (const float*)d_in[11];
    const float* bfc2 = (const float*)d_in[12];
    float* out = (float*)d_out;

    int N = in_sizes[0] / NFEAT;   // 100000
    int E = in_sizes[2];           // 1600000

    int decB = (E + 1023) / 1024;          // decode blocks (4 edges/thread)
    int aB   = (N + 15) / 16;              // passA blocks (16 nodes/block)
    int eB   = decB;                       // scatter blocks (4 edges/thread)
    int fB   = (N + 255) / 256;

    // first kernel: plain launch
    k_init<<<1 + decB + aB, 256>>>(x, ei32, Wl1, Wr1, b1, Wl2, Wr2, b2,
                                   Wfc1, bfc1, Wfc2, bfc2, N, E, decB);

    // successors: programmatic dependent launch (prologue overlaps pred drain)
    cudaLaunchAttribute at[1];
    at[0].id = cudaLaunchAttributeProgrammaticStreamSerialization;
    at[0].val.programmaticStreamSerializationAllowed = 1;

    cudaLaunchConfig_t cfg = {};
    cfg.blockDim = dim3(256, 1, 1);
    cfg.attrs    = at;
    cfg.numAttrs = 1;
    cfg.stream   = 0;

    cfg.gridDim = dim3(eB, 1, 1);
    cudaLaunchKernelEx(&cfg, k_scatter1, E);

    cfg.gridDim = dim3(eB, 1, 1);
    cudaLaunchKernelEx(&cfg, k_scatter2, E);

    cfg.gridDim = dim3(fB, 1, 1);
    cudaLaunchKernelEx(&cfg, k_final, out, N);
}